// round 10
// baseline (speedup 1.0000x reference)
#include <cuda_runtime.h>

// Shapes are fixed for this problem: B=64, C=2, H=W=512.
#define HW_SHIFT 18                 // log2(512*512)
#define HW (1 << HW_SHIFT)
#define KMAX 1000
#define NBUCK 1024                  // coarse buckets = top 10 bits of float pattern (u>>22)
#define CAP (1 << 21)               // candidate buffer per channel (2M floats)

// ---------------- device scratch (no allocations allowed) ----------------
__device__ double   g_pos_sum[2];
__device__ int      g_num_pos[2];
__device__ unsigned g_shist[2][NBUCK];   // sampled histogram of neg losses
__device__ int      g_bcut[2];           // bucket cutoff for candidate collection
__device__ int      g_cand_cnt[2];
__device__ float    g_cand[2][CAP];

// ---------------- init: zero accumulators + output ----------------
__global__ void k_init(float* dout) {
  int tid = blockIdx.x * blockDim.x + threadIdx.x;
  if (tid == 0) dout[0] = 0.0f;
  if (tid < 2) { g_pos_sum[tid] = 0.0; g_num_pos[tid] = 0; g_cand_cnt[tid] = 0; g_bcut[tid] = 0; }
  unsigned* sh = &g_shist[0][0];
  for (int i = tid; i < 2 * NBUCK; i += blockDim.x * gridDim.x) sh[i] = 0u;
}

// ---------------- pass 0: sampled histogram (1/64 of elements, contiguous
// 32-element chunks every 2048 so sampled reads stay fully coalesced) ------
__global__ void k_sample(const float* __restrict__ outp,
                         const float* __restrict__ cm,
                         const float* __restrict__ am, int N) {
  __shared__ unsigned hc[NBUCK], ha[NBUCK];
  for (int i = threadIdx.x; i < NBUCK; i += blockDim.x) { hc[i] = 0u; ha[i] = 0u; }
  __syncthreads();
  int j = blockIdx.x * blockDim.x + threadIdx.x;      // sample index
  int i = ((j >> 5) << 11) + (j & 31);                 // element index
  if (i < N) {
    int b = i >> HW_SHIFT, s = i & (HW - 1);
    size_t base = ((size_t)b) << (HW_SHIFT + 1);       // b*2*HW
    float pc = outp[base + s], pa = outp[base + HW + s];
    if (cm[i] == 0.0f) { float v = pc * pc; atomicAdd(&hc[__float_as_uint(v) >> 22], 1u); }
    if (am[i] == 0.0f) { float v = pa * pa; atomicAdd(&ha[__float_as_uint(v) >> 22], 1u); }
  }
  __syncthreads();
  for (int q = threadIdx.x; q < NBUCK; q += blockDim.x) {
    if (hc[q]) atomicAdd(&g_shist[0][q], hc[q]);
    if (ha[q]) atomicAdd(&g_shist[1][q], ha[q]);
  }
}

// ---------------- pass B: pick b_cut = largest bucket with >=64 sampled
// values at or above it  (=> ~4096 true candidates >> KMAX w.h.p.) --------
__global__ void k_bcut() {
  __shared__ unsigned ss[1024];
  __shared__ int sh_b;
  int ch = blockIdx.x, tid = threadIdx.x;
  ss[tid] = g_shist[ch][tid];
  __syncthreads();
  for (int off = 1; off < 1024; off <<= 1) {           // suffix (from-top) scan
    unsigned v = (tid + off < 1024) ? ss[tid + off] : 0u;
    __syncthreads();
    ss[tid] += v;
    __syncthreads();
  }
  if (tid == 0) sh_b = 0;                              // default: collect everything
  __syncthreads();
  unsigned here = ss[tid];
  unsigned nxt = (tid < 1023) ? ss[tid + 1] : 0u;
  if (here >= 64u && nxt < 64u) sh_b = tid;            // unique (suffix sums monotone)
  __syncthreads();
  if (tid == 0) g_bcut[ch] = sh_b;
}

// ---------------- pass A: the one full scan -------------------------------
// R9 body, 2-way unrolled: 8 independent unconditional scalar loads per
// iteration (second element address clamped, processing predicated) to raise
// per-thread MLP. 256 thr x 6 CTA/SM leaves register room for the unroll.
__global__ void __launch_bounds__(256, 6) k_main(
    const float* __restrict__ outp, const float* __restrict__ cm,
    const float* __restrict__ am, const float* __restrict__ cw,
    const float* __restrict__ aw, int N) {
  const unsigned bc0 = (unsigned)g_bcut[0];
  const unsigned bc1 = (unsigned)g_bcut[1];
  float psC = 0.f, psA = 0.f;
  int npC = 0, npA = 0;
  const int stride = blockDim.x * gridDim.x;
  const int stride2 = stride * 2;

#define PROC(pc, pa, tc, ta, II)                                            \
  do {                                                                      \
    if ((tc) != 0.0f) { float l = (pc) - (tc); l *= l; psC += l * cw[II]; npC++; } \
    else {                                                                  \
      float v = (pc) * (pc);                                                \
      if ((__float_as_uint(v) >> 22) >= bc0) {                              \
        int idx = atomicAdd(&g_cand_cnt[0], 1);                             \
        if (idx < CAP) g_cand[0][idx] = v;                                  \
      }                                                                     \
    }                                                                       \
    if ((ta) != 0.0f) { float l = (pa) - (ta); l *= l; psA += l * aw[II]; npA++; } \
    else {                                                                  \
      float v = (pa) * (pa);                                                \
      if ((__float_as_uint(v) >> 22) >= bc1) {                              \
        int idx = atomicAdd(&g_cand_cnt[1], 1);                             \
        if (idx < CAP) g_cand[1][idx] = v;                                  \
      }                                                                     \
    }                                                                       \
  } while (0)

  for (int i = blockIdx.x * blockDim.x + threadIdx.x; i < N; i += stride2) {
    int j = i + stride;
    bool has2 = (j < N);
    int jj = has2 ? j : i;                      // clamp: loads stay unconditional
    // ---- 8 independent loads, all issued before any consumption ----
    int s1 = i & (HW - 1);
    size_t b1 = ((size_t)(i >> HW_SHIFT)) << (HW_SHIFT + 1);
    int s2 = jj & (HW - 1);
    size_t b2 = ((size_t)(jj >> HW_SHIFT)) << (HW_SHIFT + 1);
    float pc1 = outp[b1 + s1];
    float pa1 = outp[b1 + HW + s1];
    float tc1 = cm[i];
    float ta1 = am[i];
    float pc2 = outp[b2 + s2];
    float pa2 = outp[b2 + HW + s2];
    float tc2 = cm[jj];
    float ta2 = am[jj];
    // ---- process ----
    PROC(pc1, pa1, tc1, ta1, i);
    if (has2) PROC(pc2, pa2, tc2, ta2, jj);
  }
#undef PROC

  for (int o = 16; o; o >>= 1) {
    psC += __shfl_down_sync(0xffffffffu, psC, o);
    psA += __shfl_down_sync(0xffffffffu, psA, o);
    npC += __shfl_down_sync(0xffffffffu, npC, o);
    npA += __shfl_down_sync(0xffffffffu, npA, o);
  }
  if ((threadIdx.x & 31) == 0) {
    atomicAdd(&g_pos_sum[0], (double)psC);
    atomicAdd(&g_pos_sum[1], (double)psA);
    atomicAdd(&g_num_pos[0], npC);
    atomicAdd(&g_num_pos[1], npA);
  }
}

// ---------------- exact boundary finder over a shared histogram ----------
// cnt/fsum[M] already built. Finds bucket t with: sum(cnt[b>t]) < need <= +cnt[t].
// Adds sum(fsum[b>t]) into *sh_acc. Leaves (t, remaining-in-t) in sh_t/sh_rem.
template <int M>
__device__ __forceinline__ void find_boundary(unsigned* cnt, float* fsum, unsigned* ss,
                                              int need, int tid,
                                              int* sh_t, int* sh_rem, double* sh_acc) {
  constexpr int CH = M / 1024;
  unsigned csum = 0;
#pragma unroll
  for (int q = 0; q < CH; q++) csum += cnt[tid * CH + q];
  ss[tid] = csum;
  __syncthreads();
  for (int off = 1; off < 1024; off <<= 1) {
    unsigned v = (tid + off < 1024) ? ss[tid + off] : 0u;
    __syncthreads();
    ss[tid] += v;
    __syncthreads();
  }
  if (tid == 0) { *sh_t = -1; *sh_rem = 0; }
  __syncthreads();
  unsigned Tj = ss[tid];
  unsigned Tj1 = (tid < 1023) ? ss[tid + 1] : 0u;
  if ((int)Tj1 < need && need <= (int)Tj) {            // exactly one thread
    int r = need - (int)Tj1;
#pragma unroll
    for (int q = CH - 1; q >= 0; q--) {
      unsigned c = cnt[tid * CH + q];
      if ((int)c < r) r -= (int)c;
      else { *sh_t = tid * CH + q; *sh_rem = r; break; }
    }
  }
  __syncthreads();
  int t = *sh_t;
  double part = 0.0;
  for (int bb = tid; bb < M; bb += 1024)
    if (bb > t) part += (double)fsum[bb];
  for (int o = 16; o; o >>= 1) part += __shfl_down_sync(0xffffffffu, part, o);
  if ((tid & 31) == 0 && part != 0.0) atomicAdd(sh_acc, part);
  __syncthreads();
}

// ---------------- pass D: exact top-k among candidates + final loss ------
__global__ void __launch_bounds__(1024) k_select(float* dout, int N) {
  __shared__ unsigned cnt[2048];
  __shared__ float fsum[2048];
  __shared__ unsigned ss[1024];
  __shared__ int sh_t, sh_rem;
  __shared__ double sh_acc;
  int ch = blockIdx.x, tid = threadIdx.x;
  int n = g_cand_cnt[ch]; if (n > CAP) n = CAP;
  int np = g_num_pos[ch];
  long long nn = (long long)N - np;
  long long kk = 4LL * (long long)np;
  if (kk > KMAX) kk = KMAX;
  if (kk > nn) kk = nn;
  if (kk < 0) kk = 0;
  int k = (int)kk;
  if (tid == 0) sh_acc = 0.0;
  __syncthreads();

  int t0 = -1, t1 = -1;
  int need = k;
  if (need > 0) {                                       // level 0: bits [31:22]
    for (int i = tid; i < 1024; i += 1024) { cnt[i] = 0u; fsum[i] = 0.f; }
    __syncthreads();
    for (int i = tid; i < n; i += 1024) {
      float v = g_cand[ch][i];
      unsigned b = __float_as_uint(v) >> 22;
      atomicAdd(&cnt[b], 1u); atomicAdd(&fsum[b], v);
    }
    __syncthreads();
    find_boundary<1024>(cnt, fsum, ss, need, tid, &sh_t, &sh_rem, &sh_acc);
    t0 = sh_t; need = sh_rem;
  }
  if (need > 0 && t0 >= 0) {                            // level 1: bits [21:11]
    for (int i = tid; i < 2048; i += 1024) { cnt[i] = 0u; fsum[i] = 0.f; }
    __syncthreads();
    for (int i = tid; i < n; i += 1024) {
      float v = g_cand[ch][i];
      unsigned u = __float_as_uint(v);
      if ((int)(u >> 22) == t0) {
        unsigned b = (u >> 11) & 2047u;
        atomicAdd(&cnt[b], 1u); atomicAdd(&fsum[b], v);
      }
    }
    __syncthreads();
    find_boundary<2048>(cnt, fsum, ss, need, tid, &sh_t, &sh_rem, &sh_acc);
    t1 = sh_t; need = sh_rem;
  }
  if (need > 0 && t1 >= 0) {                            // level 2: bits [10:0]
    for (int i = tid; i < 2048; i += 1024) { cnt[i] = 0u; fsum[i] = 0.f; }
    __syncthreads();
    for (int i = tid; i < n; i += 1024) {
      float v = g_cand[ch][i];
      unsigned u = __float_as_uint(v);
      if ((int)(u >> 22) == t0 && (int)((u >> 11) & 2047u) == t1) {
        unsigned b = u & 2047u;
        atomicAdd(&cnt[b], 1u); atomicAdd(&fsum[b], v);
      }
    }
    __syncthreads();
    find_boundary<2048>(cnt, fsum, ss, need, tid, &sh_t, &sh_rem, &sh_acc);
    int t2 = sh_t, rem2 = sh_rem;
    if (tid == 0 && t2 >= 0 && rem2 > 0) {
      // all 32 bits fixed -> identical values; take rem2 copies exactly
      float v = __uint_as_float(((unsigned)t0 << 22) | ((unsigned)t1 << 11) | (unsigned)t2);
      atomicAdd(&sh_acc, (double)rem2 * (double)v);
    }
    __syncthreads();
  }

  if (tid == 0) {
    double total = g_pos_sum[ch] + sh_acc;
    long long denom = (long long)np + k;
    float loss = (denom > 0) ? (float)(total / (double)denom) : 0.0f;
    atomicAdd(dout, loss);                              // loss_char + loss_aff
  }
}

// ---------------- launcher ----------------
extern "C" void kernel_launch(void* const* d_in, const int* in_sizes, int n_in,
                              void* d_out, int out_size) {
  const float* outp = (const float*)d_in[0];
  const float* cm   = (const float*)d_in[1];
  const float* am   = (const float*)d_in[2];
  const float* cw   = (const float*)d_in[3];
  const float* aw   = (const float*)d_in[4];
  float* o = (float*)d_out;
  int N = in_sizes[1];                                  // B*H*W = 16,777,216

  k_init<<<2, 1024>>>(o);
  int nsamp = N / 64;
  k_sample<<<(nsamp + 1023) / 1024, 1024>>>(outp, cm, am, N);
  k_bcut<<<2, 1024>>>();
  k_main<<<888, 256>>>(outp, cm, am, cw, aw, N);        // 6 CTAs/SM * 148 SMs
  k_select<<<2, 1024>>>(o, N);
}

// round 12
// speedup vs baseline: 1.0213x; 1.0213x over previous
#include <cuda_runtime.h>

// Shapes are fixed for this problem: B=64, C=2, H=W=512.
#define HW_SHIFT 18                 // log2(512*512)
#define HW (1 << HW_SHIFT)
#define KMAX 1000
#define NBUCK 1024                  // coarse buckets = top 10 bits of float pattern (u>>22)
#define CAP (1 << 21)               // candidate buffer per channel (2M floats)

// ---------------- device scratch (no allocations allowed) ----------------
__device__ double   g_pos_sum[2];
__device__ int      g_num_pos[2];
__device__ unsigned g_shist[2][NBUCK];   // sampled histogram of neg losses
__device__ int      g_bcut[2];           // bucket cutoff for candidate collection
__device__ int      g_cand_cnt[2];
__device__ float    g_cand[2][CAP];

// ---------------- init: zero accumulators + output ----------------
__global__ void k_init(float* dout) {
  int tid = blockIdx.x * blockDim.x + threadIdx.x;
  if (tid == 0) dout[0] = 0.0f;
  if (tid < 2) { g_pos_sum[tid] = 0.0; g_num_pos[tid] = 0; g_cand_cnt[tid] = 0; g_bcut[tid] = 0; }
  unsigned* sh = &g_shist[0][0];
  for (int i = tid; i < 2 * NBUCK; i += blockDim.x * gridDim.x) sh[i] = 0u;
}

// ---------------- pass 0: sampled histogram (1/64 of elements, contiguous
// 32-element chunks every 2048 so sampled reads stay fully coalesced) ------
__global__ void k_sample(const float* __restrict__ outp,
                         const float* __restrict__ cm,
                         const float* __restrict__ am, int N) {
  __shared__ unsigned hc[NBUCK], ha[NBUCK];
  for (int i = threadIdx.x; i < NBUCK; i += blockDim.x) { hc[i] = 0u; ha[i] = 0u; }
  __syncthreads();
  int j = blockIdx.x * blockDim.x + threadIdx.x;      // sample index
  int i = ((j >> 5) << 11) + (j & 31);                 // element index
  if (i < N) {
    int b = i >> HW_SHIFT, s = i & (HW - 1);
    size_t base = ((size_t)b) << (HW_SHIFT + 1);       // b*2*HW
    float pc = outp[base + s], pa = outp[base + HW + s];
    if (cm[i] == 0.0f) { float v = pc * pc; atomicAdd(&hc[__float_as_uint(v) >> 22], 1u); }
    if (am[i] == 0.0f) { float v = pa * pa; atomicAdd(&ha[__float_as_uint(v) >> 22], 1u); }
  }
  __syncthreads();
  for (int q = threadIdx.x; q < NBUCK; q += blockDim.x) {
    if (hc[q]) atomicAdd(&g_shist[0][q], hc[q]);
    if (ha[q]) atomicAdd(&g_shist[1][q], ha[q]);
  }
}

// ---------------- pass B: pick b_cut = largest bucket with >=64 sampled
// values at or above it  (=> ~4096 true candidates >> KMAX w.h.p.) --------
__global__ void k_bcut() {
  __shared__ unsigned ss[1024];
  __shared__ int sh_b;
  int ch = blockIdx.x, tid = threadIdx.x;
  ss[tid] = g_shist[ch][tid];
  __syncthreads();
  for (int off = 1; off < 1024; off <<= 1) {           // suffix (from-top) scan
    unsigned v = (tid + off < 1024) ? ss[tid + off] : 0u;
    __syncthreads();
    ss[tid] += v;
    __syncthreads();
  }
  if (tid == 0) sh_b = 0;                              // default: collect everything
  __syncthreads();
  unsigned here = ss[tid];
  unsigned nxt = (tid < 1023) ? ss[tid + 1] : 0u;
  if (here >= 64u && nxt < 64u) sh_b = tid;            // unique (suffix sums monotone)
  __syncthreads();
  if (tid == 0) g_bcut[ch] = sh_b;
}

// ---------------- pass A: the one full scan -------------------------------
// R9 geometry (256 thr x 8 CTA/SM, grid 1184) with ONE change: cw/aw are
// loaded UNCONDITIONALLY alongside the other 4 loads, so all 6 loads per
// element are independent and front-batched. This removes the cm->branch->cw
// dependent-DRAM-latency chain that capped R9/R10 at ~45% DRAM.
__global__ void __launch_bounds__(256, 8) k_main(
    const float* __restrict__ outp, const float* __restrict__ cm,
    const float* __restrict__ am, const float* __restrict__ cw,
    const float* __restrict__ aw, int N) {
  const unsigned bc0 = (unsigned)g_bcut[0];
  const unsigned bc1 = (unsigned)g_bcut[1];
  float psC = 0.f, psA = 0.f;
  int npC = 0, npA = 0;
  int stride = blockDim.x * gridDim.x;
  for (int i = blockIdx.x * blockDim.x + threadIdx.x; i < N; i += stride) {
    int b = i >> HW_SHIFT, s = i & (HW - 1);
    size_t base = ((size_t)b) << (HW_SHIFT + 1);
    // ---- 6 independent loads, no load depends on another ----
    float pc = outp[base + s];
    float pa = outp[base + HW + s];
    float tc = cm[i];
    float ta = am[i];
    float wc = cw[i];
    float wa = aw[i];
    // ---- process (branches consume; no loads inside) ----
    if (tc != 0.0f) { float l = pc - tc; l *= l; psC += l * wc; npC++; }
    else {
      float v = pc * pc;
      if ((__float_as_uint(v) >> 22) >= bc0) {
        int idx = atomicAdd(&g_cand_cnt[0], 1);
        if (idx < CAP) g_cand[0][idx] = v;
      }
    }
    if (ta != 0.0f) { float l = pa - ta; l *= l; psA += l * wa; npA++; }
    else {
      float v = pa * pa;
      if ((__float_as_uint(v) >> 22) >= bc1) {
        int idx = atomicAdd(&g_cand_cnt[1], 1);
        if (idx < CAP) g_cand[1][idx] = v;
      }
    }
  }
  for (int o = 16; o; o >>= 1) {
    psC += __shfl_down_sync(0xffffffffu, psC, o);
    psA += __shfl_down_sync(0xffffffffu, psA, o);
    npC += __shfl_down_sync(0xffffffffu, npC, o);
    npA += __shfl_down_sync(0xffffffffu, npA, o);
  }
  if ((threadIdx.x & 31) == 0) {
    atomicAdd(&g_pos_sum[0], (double)psC);
    atomicAdd(&g_pos_sum[1], (double)psA);
    atomicAdd(&g_num_pos[0], npC);
    atomicAdd(&g_num_pos[1], npA);
  }
}

// ---------------- exact boundary finder over a shared histogram ----------
// cnt/fsum[M] already built. Finds bucket t with: sum(cnt[b>t]) < need <= +cnt[t].
// Adds sum(fsum[b>t]) into *sh_acc. Leaves (t, remaining-in-t) in sh_t/sh_rem.
template <int M>
__device__ __forceinline__ void find_boundary(unsigned* cnt, float* fsum, unsigned* ss,
                                              int need, int tid,
                                              int* sh_t, int* sh_rem, double* sh_acc) {
  constexpr int CH = M / 1024;
  unsigned csum = 0;
#pragma unroll
  for (int q = 0; q < CH; q++) csum += cnt[tid * CH + q];
  ss[tid] = csum;
  __syncthreads();
  for (int off = 1; off < 1024; off <<= 1) {
    unsigned v = (tid + off < 1024) ? ss[tid + off] : 0u;
    __syncthreads();
    ss[tid] += v;
    __syncthreads();
  }
  if (tid == 0) { *sh_t = -1; *sh_rem = 0; }
  __syncthreads();
  unsigned Tj = ss[tid];
  unsigned Tj1 = (tid < 1023) ? ss[tid + 1] : 0u;
  if ((int)Tj1 < need && need <= (int)Tj) {            // exactly one thread
    int r = need - (int)Tj1;
#pragma unroll
    for (int q = CH - 1; q >= 0; q--) {
      unsigned c = cnt[tid * CH + q];
      if ((int)c < r) r -= (int)c;
      else { *sh_t = tid * CH + q; *sh_rem = r; break; }
    }
  }
  __syncthreads();
  int t = *sh_t;
  double part = 0.0;
  for (int bb = tid; bb < M; bb += 1024)
    if (bb > t) part += (double)fsum[bb];
  for (int o = 16; o; o >>= 1) part += __shfl_down_sync(0xffffffffu, part, o);
  if ((tid & 31) == 0 && part != 0.0) atomicAdd(sh_acc, part);
  __syncthreads();
}

// ---------------- pass D: exact top-k among candidates + final loss ------
__global__ void __launch_bounds__(1024) k_select(float* dout, int N) {
  __shared__ unsigned cnt[2048];
  __shared__ float fsum[2048];
  __shared__ unsigned ss[1024];
  __shared__ int sh_t, sh_rem;
  __shared__ double sh_acc;
  int ch = blockIdx.x, tid = threadIdx.x;
  int n = g_cand_cnt[ch]; if (n > CAP) n = CAP;
  int np = g_num_pos[ch];
  long long nn = (long long)N - np;
  long long kk = 4LL * (long long)np;
  if (kk > KMAX) kk = KMAX;
  if (kk > nn) kk = nn;
  if (kk < 0) kk = 0;
  int k = (int)kk;
  if (tid == 0) sh_acc = 0.0;
  __syncthreads();

  int t0 = -1, t1 = -1;
  int need = k;
  if (need > 0) {                                       // level 0: bits [31:22]
    for (int i = tid; i < 1024; i += 1024) { cnt[i] = 0u; fsum[i] = 0.f; }
    __syncthreads();
    for (int i = tid; i < n; i += 1024) {
      float v = g_cand[ch][i];
      unsigned b = __float_as_uint(v) >> 22;
      atomicAdd(&cnt[b], 1u); atomicAdd(&fsum[b], v);
    }
    __syncthreads();
    find_boundary<1024>(cnt, fsum, ss, need, tid, &sh_t, &sh_rem, &sh_acc);
    t0 = sh_t; need = sh_rem;
  }
  if (need > 0 && t0 >= 0) {                            // level 1: bits [21:11]
    for (int i = tid; i < 2048; i += 1024) { cnt[i] = 0u; fsum[i] = 0.f; }
    __syncthreads();
    for (int i = tid; i < n; i += 1024) {
      float v = g_cand[ch][i];
      unsigned u = __float_as_uint(v);
      if ((int)(u >> 22) == t0) {
        unsigned b = (u >> 11) & 2047u;
        atomicAdd(&cnt[b], 1u); atomicAdd(&fsum[b], v);
      }
    }
    __syncthreads();
    find_boundary<2048>(cnt, fsum, ss, need, tid, &sh_t, &sh_rem, &sh_acc);
    t1 = sh_t; need = sh_rem;
  }
  if (need > 0 && t1 >= 0) {                            // level 2: bits [10:0]
    for (int i = tid; i < 2048; i += 1024) { cnt[i] = 0u; fsum[i] = 0.f; }
    __syncthreads();
    for (int i = tid; i < n; i += 1024) {
      float v = g_cand[ch][i];
      unsigned u = __float_as_uint(v);
      if ((int)(u >> 22) == t0 && (int)((u >> 11) & 2047u) == t1) {
        unsigned b = u & 2047u;
        atomicAdd(&cnt[b], 1u); atomicAdd(&fsum[b], v);
      }
    }
    __syncthreads();
    find_boundary<2048>(cnt, fsum, ss, need, tid, &sh_t, &sh_rem, &sh_acc);
    int t2 = sh_t, rem2 = sh_rem;
    if (tid == 0 && t2 >= 0 && rem2 > 0) {
      // all 32 bits fixed -> identical values; take rem2 copies exactly
      float v = __uint_as_float(((unsigned)t0 << 22) | ((unsigned)t1 << 11) | (unsigned)t2);
      atomicAdd(&sh_acc, (double)rem2 * (double)v);
    }
    __syncthreads();
  }

  if (tid == 0) {
    double total = g_pos_sum[ch] + sh_acc;
    long long denom = (long long)np + k;
    float loss = (denom > 0) ? (float)(total / (double)denom) : 0.0f;
    atomicAdd(dout, loss);                              // loss_char + loss_aff
  }
}

// ---------------- launcher ----------------
extern "C" void kernel_launch(void* const* d_in, const int* in_sizes, int n_in,
                              void* d_out, int out_size) {
  const float* outp = (const float*)d_in[0];
  const float* cm   = (const float*)d_in[1];
  const float* am   = (const float*)d_in[2];
  const float* cw   = (const float*)d_in[3];
  const float* aw   = (const float*)d_in[4];
  float* o = (float*)d_out;
  int N = in_sizes[1];                                  // B*H*W = 16,777,216

  k_init<<<2, 1024>>>(o);
  int nsamp = N / 64;
  k_sample<<<(nsamp + 1023) / 1024, 1024>>>(outp, cm, am, N);
  k_bcut<<<2, 1024>>>();
  k_main<<<1184, 256>>>(outp, cm, am, cw, aw, N);       // 8 CTAs/SM * 148 SMs, 100% occ
  k_select<<<2, 1024>>>(o, N);
}